// round 6
// baseline (speedup 1.0000x reference)
#include <cuda_runtime.h>

#define N_NODES 50000
#define N_EDGES 200000
#define F_IN 100
#define HID 1024

#define NB_DEG   ((N_NODES + 255) / 256)          // 196 blocks, per-node work
#define NB_NODE  ((N_NODES * 32 + 255) / 256)     // 6250 blocks, warp-per-node
#define NB_EDGE  ((N_EDGES + 255) / 256)          // 782 blocks, thread-per-edge
#define NB_E2    ((N_EDGES / 2 + 255) / 256)      // 391 blocks, 2 edges/thread

// Scratch (no device allocation allowed)
__device__ float g_w[F_IN];
__device__ float g_c;
__device__ float g_deg[N_NODES];
__device__ float g_dinv[N_NODES];
__device__ float g_s[N_NODES];    // s[n] = x[n]·w
__device__ float g_p[N_NODES];    // p[n] = s[n] * dinv[n]
__device__ float g_acc[N_NODES];  // acc[n] = sum_{s->n} p[s]  (dinv factored out)
__device__ int   g_is64;

// ---------------------------------------------------------------------------
// K1 (fused setup): block 0 = dtype detect, blocks 1..101 = head fold,
// next 196 = degree init to 1.0 (self loop), last 196 = zero acc.
// All independent.
// ---------------------------------------------------------------------------
__global__ void setup_kernel(const int* __restrict__ ebuf,
                             const float* __restrict__ W1,
                             const float* __restrict__ b1,
                             const float* __restrict__ Wh,
                             const float* __restrict__ bh) {
    int blk = blockIdx.x;
    int t = threadIdx.x;

    if (blk == 0) {
        // int64-little-endian edge values < 50000 => every odd 32-bit word is 0.
        __shared__ int any_nonzero;
        if (t == 0) any_nonzero = 0;
        __syncthreads();
        for (int i = t; i < 1024; i += blockDim.x)
            if (ebuf[2 * i + 1] != 0) any_nonzero = 1;
        __syncthreads();
        if (t == 0) g_is64 = any_nonzero ? 0 : 1;
        return;
    }
    if (blk <= F_IN + 1) {
        int b = blk - 1;  // 0..100
        __shared__ float red[256];
        float acc = 0.f;
        if (b < F_IN) {
            const float* row = W1 + (long long)b * HID;
            for (int k = t; k < HID; k += 256) acc += row[k] * Wh[k];
        } else {
            for (int k = t; k < HID; k += 256) acc += b1[k] * Wh[k];
        }
        red[t] = acc;
        __syncthreads();
        for (int s = 128; s > 0; s >>= 1) {
            if (t < s) red[t] += red[t + s];
            __syncthreads();
        }
        if (t == 0) {
            if (b < F_IN) g_w[b] = red[0];
            else          g_c   = red[0] + bh[0];
        }
        return;
    }
    if (blk < F_IN + 2 + NB_DEG) {
        int i = (blk - (F_IN + 2)) * 256 + t;
        if (i < N_NODES) g_deg[i] = 1.0f;
        return;
    }
    // zero message accumulator (required every graph replay)
    int i = (blk - (F_IN + 2 + NB_DEG)) * 256 + t;
    if (i < N_NODES) g_acc[i] = 0.0f;
}

__device__ __forceinline__ int load_edge(const int* ebuf, long long pos) {
    if (g_is64) return ((const int2*)ebuf)[pos].x;   // coalesced 8B load, lo word
    return ebuf[pos];
}

// ---------------------------------------------------------------------------
// K2 (fused): blocks [0, NB_EDGE) = degree atomics over edges (launched FIRST
// so they finish under cover of the long x-stream); blocks [NB_EDGE, ...) =
// warp-per-node dot product s[n] = x[n]·w.
// ---------------------------------------------------------------------------
__global__ void dot_and_deg_kernel(const float* __restrict__ x,
                                   const int* __restrict__ ebuf) {
    int blk = blockIdx.x;
    int t = threadIdx.x;

    if (blk < NB_EDGE) {
        int e = blk * 256 + t;
        if (e < N_EDGES) {
            int dst = load_edge(ebuf, (long long)N_EDGES + e);
            if (dst >= 0 && dst < N_NODES)
                atomicAdd(&g_deg[dst], 1.0f);
        }
        return;
    }

    __shared__ float sw[F_IN];
    for (int i = t; i < F_IN; i += blockDim.x) sw[i] = g_w[i];
    __syncthreads();

    int node = ((blk - NB_EDGE) * 256 + t) >> 5;
    int lane = t & 31;
    if (node >= N_NODES) return;

    const float* xr = x + (long long)node * F_IN;
    float acc = xr[lane]      * sw[lane]
              + xr[lane + 32] * sw[lane + 32]
              + xr[lane + 64] * sw[lane + 64];
    if (lane < 4) acc += xr[lane + 96] * sw[lane + 96];

    #pragma unroll
    for (int o = 16; o > 0; o >>= 1)
        acc += __shfl_down_sync(0xffffffffu, acc, o);

    if (lane == 0) g_s[node] = acc;
}

// ---------------------------------------------------------------------------
// K3: per-node finalize: dinv, p, and out = self-loop msg + folded bias
// ---------------------------------------------------------------------------
__global__ void node_finalize(float* __restrict__ out) {
    int n = blockIdx.x * blockDim.x + threadIdx.x;
    if (n < N_NODES) {
        float d = rsqrtf(g_deg[n]);       // deg >= 1 always (self loop)
        float s = g_s[n];
        g_dinv[n] = d;
        g_p[n]    = s * d;
        out[n]    = g_c + s * d * d;
    }
}

// ---------------------------------------------------------------------------
// K4: edge scatter, 2 edges/thread: acc[dst] += p[src].
// dinv[dst] is factored out of the sum -> only ONE divergent gather per edge.
// ---------------------------------------------------------------------------
__global__ void edge_scatter(const int* __restrict__ ebuf) {
    int e = (blockIdx.x * 256 + threadIdx.x) * 2;
    if (e >= N_EDGES) return;   // N_EDGES even: no partial pairs

    int s0, s1, d0, d1;
    if (g_is64) {
        int4 vs = ((const int4*)ebuf)[e >> 1];
        int4 vd = ((const int4*)ebuf)[((long long)N_EDGES + e) >> 1];
        s0 = vs.x; s1 = vs.z; d0 = vd.x; d1 = vd.z;
    } else {
        int2 vs = ((const int2*)ebuf)[e >> 1];
        int2 vd = ((const int2*)ebuf)[((long long)N_EDGES + e) >> 1];
        s0 = vs.x; s1 = vs.y; d0 = vd.x; d1 = vd.y;
    }

    bool v0 = (unsigned)s0 < N_NODES && (unsigned)d0 < N_NODES;
    bool v1 = (unsigned)s1 < N_NODES && (unsigned)d1 < N_NODES;

    float p0 = v0 ? g_p[s0] : 0.f;
    float p1 = v1 ? g_p[s1] : 0.f;

    if (v0) atomicAdd(&g_acc[d0], p0);
    if (v1) atomicAdd(&g_acc[d1], p1);
}

// ---------------------------------------------------------------------------
// K5: apply factored normalization: out[n] += dinv[n] * acc[n]
// ---------------------------------------------------------------------------
__global__ void out_add(float* __restrict__ out) {
    int n = blockIdx.x * blockDim.x + threadIdx.x;
    if (n < N_NODES)
        out[n] = fmaf(g_dinv[n], g_acc[n], out[n]);
}

extern "C" void kernel_launch(void* const* d_in, const int* in_sizes, int n_in,
                              void* d_out, int out_size) {
    const float* state = (const float*)d_in[0];  // [N, 100, 1] f32
    const int*   ebuf  = (const int*)  d_in[1];  // [2, 200000] int32/int64 layout
    const float* W1    = (const float*)d_in[2];  // [100, 1024]
    const float* b1    = (const float*)d_in[3];  // [1024]
    const float* Wh    = (const float*)d_in[4];  // [1024, 1]
    const float* bh    = (const float*)d_in[5];  // [1]
    float* out = (float*)d_out;                  // [N, 1]

    setup_kernel      <<<1 + (F_IN + 1) + 2 * NB_DEG, 256>>>(ebuf, W1, b1, Wh, bh);
    dot_and_deg_kernel<<<NB_EDGE + NB_NODE, 256>>>(state, ebuf);
    node_finalize     <<<NB_DEG, 256>>>(out);
    edge_scatter      <<<NB_E2, 256>>>(ebuf);
    out_add           <<<NB_DEG, 256>>>(out);
}